// round 1
// baseline (speedup 1.0000x reference)
#include <cuda_runtime.h>
#include <math.h>

#define BB 8
#define SS 4
#define NN 8192
#define MM 50
#define BSN (BB*SS*NN)   // 262144
#define COST_THRESH 50.0f

// ---------------- scratch (no allocations allowed) ----------------
__device__ int      g_assign[BSN];
__device__ unsigned g_flag[BB*SS];
// 0: center_sum, 1: n_pos, 2: sum_pos softplus(-x), 3: sum_neg softplus(x), 4: sum_unmatched
__device__ double   g_acc[5];

// ---------------- init ----------------
__global__ void init_kernel() {
    int i = blockIdx.x * blockDim.x + threadIdx.x;
    int stride = gridDim.x * blockDim.x;
    for (int k = i; k < BSN; k += stride) g_assign[k] = -1;
    if (i < BB*SS) g_flag[i] = 0u;
    if (i < 5)     g_acc[i]  = 0.0;
}

// ---------------- per-(b,s,m) top-10 selection ----------------
// One block per (b,s,m). Computes all 8192 distances into smem, then 10
// rounds of block-argmin (ties -> lowest index, matching jax.lax.top_k).
// Entries with dist<50 are the masked-top-k picks -> atomicMax into assign.
// If the gt is valid but NO pick is <50, it's unmatched: accumulate the
// exp(-d/2)*(1-score) term over the 5 nearest (first 5 of sorted list).
__global__ void topk_kernel(const float* __restrict__ pb,
                            const float* __restrict__ gtb,
                            const int*   __restrict__ n_gt,
                            const float* __restrict__ scores) {
    const int m = blockIdx.x, s = blockIdx.y, b = blockIdx.z;
    if (m >= n_gt[b]) return;   // invalid gt: all-inf cost, contributes nothing

    __shared__ float sd[NN];
    __shared__ float wv[8];
    __shared__ int   wi[8];
    __shared__ float topv[10];
    __shared__ int   topi[10];

    const int tid = threadIdx.x;

    const float gx = gtb[(b*MM + m)*7 + 0];
    const float gy = gtb[(b*MM + m)*7 + 1];
    const float gz = gtb[(b*MM + m)*7 + 2];

    const float* base = pb + ((size_t)(b*SS + s) * NN) * 7;

    for (int k = tid; k < NN; k += 256) {
        float dx = base[k*7 + 0] - gx;
        float dy = base[k*7 + 1] - gy;
        float dz = base[k*7 + 2] - gz;
        sd[k] = sqrtf(dx*dx + dy*dy + dz*dz);
    }
    __syncthreads();

    for (int it = 0; it < 10; ++it) {
        float best = 3.4e38f;
        int   bi   = 0;
        for (int k = tid; k < NN; k += 256) {
            float v = sd[k];
            if (v < best) { best = v; bi = k; }   // strict < keeps lowest idx in-thread
        }
        #pragma unroll
        for (int off = 16; off; off >>= 1) {
            float ov = __shfl_down_sync(0xffffffffu, best, off);
            int   oi = __shfl_down_sync(0xffffffffu, bi,   off);
            if (ov < best || (ov == best && oi < bi)) { best = ov; bi = oi; }
        }
        if ((tid & 31) == 0) { wv[tid >> 5] = best; wi[tid >> 5] = bi; }
        __syncthreads();
        if (tid == 0) {
            #pragma unroll
            for (int w = 1; w < 8; ++w)
                if (wv[w] < best || (wv[w] == best && wi[w] < bi)) { best = wv[w]; bi = wi[w]; }
            topv[it] = best; topi[it] = bi;
            sd[bi] = 3.4e38f;   // remove for next round
        }
        __syncthreads();
    }

    if (tid == 0) {
        bool matched = false;
        const int abase = (b*SS + s) * NN;
        #pragma unroll
        for (int j = 0; j < 10; ++j) {
            if (topv[j] < COST_THRESH) {
                atomicMax(&g_assign[abase + topi[j]], m);
                matched = true;
            }
        }
        if (!matched) {
            float pg = 0.f;
            #pragma unroll
            for (int j = 0; j < 5; ++j)
                pg += expf(-topv[j] * 0.5f) * (1.0f - scores[abase + topi[j]]);
            pg *= 0.2f;
            atomicAdd(&g_acc[4], (double)pg);
            atomicOr(&g_flag[b*SS + s], 1u);
        }
    }
}

// ---------------- fused reduction over all (b,s,n) ----------------
__global__ void reduce_kernel(const float* __restrict__ pb,
                              const float* __restrict__ scores,
                              const float* __restrict__ gtb) {
    const int gid = blockIdx.x * blockDim.x + threadIdx.x;
    const int stride = gridDim.x * blockDim.x;

    double c_sum = 0.0, sp1 = 0.0, sp2 = 0.0, np = 0.0;

    for (int i = gid; i < BSN; i += stride) {
        const int a = g_assign[i];
        const float x = scores[i];
        const float l1p = log1pf(expf(-fabsf(x)));   // shared tail of softplus(±x)
        if (a >= 0) {
            np  += 1.0;
            sp1 += (double)(fmaxf(-x, 0.f) + l1p);    // softplus(-x)
            const int bb = i >> 15;                   // / (S*N) = 32768
            const float* p = pb  + (size_t)i * 7;
            const float* g = gtb + (size_t)(bb*MM + a) * 7;
            #pragma unroll
            for (int d = 0; d < 3; ++d) {
                float dd = p[d] - g[d];
                float ad = fabsf(dd);
                c_sum += (double)((ad < 1.f) ? 0.5f*ad*ad : ad - 0.5f);
            }
        } else {
            sp2 += (double)(fmaxf(x, 0.f) + l1p);     // softplus(x)
        }
    }

    // warp reduce
    #pragma unroll
    for (int off = 16; off; off >>= 1) {
        c_sum += __shfl_down_sync(0xffffffffu, c_sum, off);
        sp1   += __shfl_down_sync(0xffffffffu, sp1,   off);
        sp2   += __shfl_down_sync(0xffffffffu, sp2,   off);
        np    += __shfl_down_sync(0xffffffffu, np,    off);
    }
    __shared__ double sm[4][8];
    const int w = threadIdx.x >> 5;
    if ((threadIdx.x & 31) == 0) { sm[0][w]=c_sum; sm[1][w]=sp1; sm[2][w]=sp2; sm[3][w]=np; }
    __syncthreads();
    if (threadIdx.x == 0) {
        #pragma unroll
        for (int k = 1; k < 8; ++k) { c_sum+=sm[0][k]; sp1+=sm[1][k]; sp2+=sm[2][k]; np+=sm[3][k]; }
        atomicAdd(&g_acc[0], c_sum);
        atomicAdd(&g_acc[1], np);
        atomicAdd(&g_acc[2], sp1);
        atomicAdd(&g_acc[3], sp2);
    }
}

// ---------------- final scalar combine ----------------
__global__ void final_kernel(float* __restrict__ out,
                             const float* __restrict__ wc,
                             const float* __restrict__ wo,
                             const float* __restrict__ wu) {
    const double npos = g_acc[1];
    const double loss_center = g_acc[0] / fmax(npos * 3.0, 1.0);
    const double nneg = (double)BSN - npos;
    const double pw = fmin(10.0, nneg / fmax(npos, 1.0));
    const double loss_obj = (pw * g_acc[2] + g_acc[3]) / (double)BSN;
    int ne = 0;
    #pragma unroll
    for (int k = 0; k < BB*SS; ++k) ne += (g_flag[k] ? 1 : 0);
    const double loss_unm = g_acc[4] / fmax((double)ne, 1.0);
    out[0] = (float)(loss_center * (double)wc[0] +
                     loss_obj    * (double)wo[0] +
                     loss_unm    * (double)wu[0]);
}

// ---------------- launch ----------------
extern "C" void kernel_launch(void* const* d_in, const int* in_sizes, int n_in,
                              void* d_out, int out_size) {
    const float* pb     = (const float*)d_in[0];   // pred_boxes  [8,4,8192,7]
    // d_in[1] pred_classes: unused
    const float* scores = (const float*)d_in[2];   // pred_scores [8,4,8192]
    const float* gtb    = (const float*)d_in[3];   // gt_boxes    [8,50,7]
    // d_in[4] gt_classes: unused
    const int*   n_gt   = (const int*)d_in[5];     // [8]
    const float* wc     = (const float*)d_in[6];
    const float* wo     = (const float*)d_in[7];
    const float* wu     = (const float*)d_in[8];
    // d_in[9] epoch: unused
    float* out = (float*)d_out;

    init_kernel<<<256, 256>>>();
    dim3 grid(MM, SS, BB);
    topk_kernel<<<grid, 256>>>(pb, gtb, n_gt, scores);
    reduce_kernel<<<256, 256>>>(pb, scores, gtb);
    final_kernel<<<1, 1>>>(out, wc, wo, wu);
}

// round 2
// speedup vs baseline: 1.5450x; 1.5450x over previous
#include <cuda_runtime.h>
#include <math.h>

#define BB 8
#define SS 4
#define NN 8192
#define MM 50
#define BSN (BB*SS*NN)   // 262144
#define INF_F 3.4e38f

// ---------------- scratch (no allocations allowed) ----------------
__device__ float    g_px[BSN];
__device__ float    g_py[BSN];
__device__ float    g_pz[BSN];
__device__ int      g_assign[BSN];
__device__ unsigned g_flag[BB*SS];
// 0: center_sum, 1: n_pos, 2: sum_pos softplus(-x), 3: sum_neg softplus(x), 4: sum_unmatched
__device__ double   g_acc[5];
__device__ unsigned g_done;

// ---------------- transpose + init (1 launch) ----------------
__global__ void prep_kernel(const float* __restrict__ pb) {
    int i = blockIdx.x * blockDim.x + threadIdx.x;
    if (i < BSN) {
        const float* p = pb + (size_t)i * 7;
        g_px[i] = p[0];
        g_py[i] = p[1];
        g_pz[i] = p[2];
        g_assign[i] = -1;
    }
    if (i < BB*SS) g_flag[i] = 0u;
    if (i < 5)     g_acc[i]  = 0.0;
    if (i == 0)    g_done    = 0u;
}

// lexicographic (val, idx) warp min -> valid on lane 0
__device__ __forceinline__ void warp_min(float& v, int& i) {
    #pragma unroll
    for (int off = 16; off; off >>= 1) {
        float ov = __shfl_down_sync(0xffffffffu, v, off);
        int   oi = __shfl_down_sync(0xffffffffu, i, off);
        if (ov < v || (ov == v && oi < i)) { v = ov; i = oi; }
    }
}

// ---------------- per-(b,s,m-pair) top-10 selection ----------------
// One block per (b, s, m-pair). Shared planar coordinate loads feed TWO
// gt distance arrays. Segment minima (64 segs of 128) are built during the
// distance pass; each of the 10 selection rounds is a 64-way warp reduce
// plus one 128-element segment rescan. Warp 0 selects for m0, warp 1 for m1.
__global__ void topk_kernel(const float* __restrict__ gtb,
                            const int*   __restrict__ n_gt,
                            const float* __restrict__ scores) {
    extern __shared__ float smem[];
    float* sd0 = smem;            // [8192]
    float* sd1 = smem + NN;       // [8192]
    __shared__ float segv[2][64];
    __shared__ int   segi[2][64];

    const int mp = blockIdx.x, s = blockIdx.y, b = blockIdx.z;
    const int m0 = mp * 2, m1 = m0 + 1;
    const int ngt = n_gt[b];
    if (m0 >= ngt) return;                 // m1 checked later

    const int tid  = threadIdx.x;
    const int w    = tid >> 5;
    const int lane = tid & 31;

    const float g0x = gtb[(b*MM + m0)*7 + 0];
    const float g0y = gtb[(b*MM + m0)*7 + 1];
    const float g0z = gtb[(b*MM + m0)*7 + 2];
    const float g1x = gtb[(b*MM + m1)*7 + 0];
    const float g1y = gtb[(b*MM + m1)*7 + 1];
    const float g1z = gtb[(b*MM + m1)*7 + 2];

    const int gbase = (b*SS + s) * NN;

    // ---- phase 1: distances + fused segment minima ----
    {
        const int base = w * 1024;
        float rv0 = INF_F, rv1 = INF_F;
        int   ri0 = 0,     ri1 = 0;
        #pragma unroll
        for (int i = 0; i < 32; ++i) {
            const int e = base + i*32 + lane;
            const float x = g_px[gbase + e];
            const float y = g_py[gbase + e];
            const float z = g_pz[gbase + e];
            float dx = x - g0x, dy = y - g0y, dz = z - g0z;
            const float d0 = fmaf(dx, dx, fmaf(dy, dy, dz*dz));
            dx = x - g1x; dy = y - g1y; dz = z - g1z;
            const float d1 = fmaf(dx, dx, fmaf(dy, dy, dz*dz));
            sd0[e] = d0;
            sd1[e] = d1;
            if (d0 < rv0) { rv0 = d0; ri0 = e; }
            if (d1 < rv1) { rv1 = d1; ri1 = e; }
            if ((i & 3) == 3) {
                float tv0 = rv0; int ti0 = ri0;
                float tv1 = rv1; int ti1 = ri1;
                warp_min(tv0, ti0);
                warp_min(tv1, ti1);
                if (lane == 0) {
                    const int sg = w*8 + (i >> 2);
                    segv[0][sg] = tv0; segi[0][sg] = ti0;
                    segv[1][sg] = tv1; segi[1][sg] = ti1;
                }
                rv0 = INF_F; rv1 = INF_F; ri0 = 0; ri1 = 0;
            }
        }
    }
    __syncthreads();

    // ---- phase 2: 10 selection rounds (warp 0 -> m0, warp 1 -> m1) ----
    if (w < 2) {
        if (w == 1 && m1 >= ngt) return;   // whole warp exits together
        float* sd  = (w == 0) ? sd0 : sd1;
        float* sgv = segv[w];
        int*   sgi = segi[w];

        float topv[10];
        int   topi[10];
        #pragma unroll
        for (int it = 0; it < 10; ++it) {
            // min over 64 segments (2 per lane)
            float v  = sgv[lane];      int ei  = sgi[lane];
            float v2 = sgv[lane + 32]; int ei2 = sgi[lane + 32];
            if (v2 < v || (v2 == v && ei2 < ei)) { v = v2; ei = ei2; }
            warp_min(v, ei);
            v  = __shfl_sync(0xffffffffu, v,  0);
            ei = __shfl_sync(0xffffffffu, ei, 0);
            topv[it] = v; topi[it] = ei;
            const int sg = ei >> 7;
            if (lane == 0) sd[ei] = INF_F;
            __syncwarp();
            // rescan the affected 128-element segment
            const int rb = sg*128 + lane*4;
            float nv = INF_F; int ni = rb;
            #pragma unroll
            for (int j = 0; j < 4; ++j) {
                const float t = sd[rb + j];
                if (t < nv) { nv = t; ni = rb + j; }
            }
            warp_min(nv, ni);
            if (lane == 0) { sgv[sg] = nv; sgi[sg] = ni; }
            __syncwarp();
        }

        if (lane == 0) {
            const int mm = (w == 0) ? m0 : m1;
            bool matched = false;
            #pragma unroll
            for (int j = 0; j < 10; ++j) {
                if (sqrtf(topv[j]) < 50.0f) {
                    atomicMax(&g_assign[gbase + topi[j]], mm);
                    matched = true;
                }
            }
            if (!matched) {
                float pg = 0.f;
                #pragma unroll
                for (int j = 0; j < 5; ++j)
                    pg += expf(-sqrtf(topv[j]) * 0.5f) * (1.0f - scores[gbase + topi[j]]);
                atomicAdd(&g_acc[4], (double)(pg * 0.2f));
                atomicOr(&g_flag[b*SS + s], 1u);
            }
        }
    }
}

// ---------------- fused reduction + final combine (last block) ----------------
__global__ void reduce_kernel(const float* __restrict__ scores,
                              const float* __restrict__ gtb,
                              float* __restrict__ out,
                              const float* __restrict__ wc,
                              const float* __restrict__ wo,
                              const float* __restrict__ wu) {
    const int gid = blockIdx.x * blockDim.x + threadIdx.x;
    const int stride = gridDim.x * blockDim.x;

    double c_sum = 0.0, sp1 = 0.0, sp2 = 0.0, np = 0.0;

    for (int i = gid; i < BSN; i += stride) {
        const int a = g_assign[i];
        const float x = scores[i];
        const float l1p = log1pf(expf(-fabsf(x)));   // shared tail of softplus(+-x)
        if (a >= 0) {
            np  += 1.0;
            sp1 += (double)(fmaxf(-x, 0.f) + l1p);    // softplus(-x)
            const int bb = i >> 15;                   // / (S*N)
            const float* g = gtb + (size_t)(bb*MM + a) * 7;
            float dd, ad;
            dd = g_px[i] - g[0]; ad = fabsf(dd);
            c_sum += (double)((ad < 1.f) ? 0.5f*ad*ad : ad - 0.5f);
            dd = g_py[i] - g[1]; ad = fabsf(dd);
            c_sum += (double)((ad < 1.f) ? 0.5f*ad*ad : ad - 0.5f);
            dd = g_pz[i] - g[2]; ad = fabsf(dd);
            c_sum += (double)((ad < 1.f) ? 0.5f*ad*ad : ad - 0.5f);
        } else {
            sp2 += (double)(fmaxf(x, 0.f) + l1p);     // softplus(x)
        }
    }

    #pragma unroll
    for (int off = 16; off; off >>= 1) {
        c_sum += __shfl_down_sync(0xffffffffu, c_sum, off);
        sp1   += __shfl_down_sync(0xffffffffu, sp1,   off);
        sp2   += __shfl_down_sync(0xffffffffu, sp2,   off);
        np    += __shfl_down_sync(0xffffffffu, np,    off);
    }
    __shared__ double sm[4][8];
    const int w = threadIdx.x >> 5;
    if ((threadIdx.x & 31) == 0) { sm[0][w]=c_sum; sm[1][w]=sp1; sm[2][w]=sp2; sm[3][w]=np; }
    __syncthreads();
    if (threadIdx.x == 0) {
        #pragma unroll
        for (int k = 1; k < 8; ++k) { c_sum+=sm[0][k]; sp1+=sm[1][k]; sp2+=sm[2][k]; np+=sm[3][k]; }
        atomicAdd(&g_acc[0], c_sum);
        atomicAdd(&g_acc[1], np);
        atomicAdd(&g_acc[2], sp1);
        atomicAdd(&g_acc[3], sp2);
        __threadfence();
        const unsigned t = atomicAdd(&g_done, 1u);
        if (t == gridDim.x - 1) {
            const double npos = g_acc[1];
            const double loss_center = g_acc[0] / fmax(npos * 3.0, 1.0);
            const double nneg = (double)BSN - npos;
            const double pw = fmin(10.0, nneg / fmax(npos, 1.0));
            const double loss_obj = (pw * g_acc[2] + g_acc[3]) / (double)BSN;
            int ne = 0;
            #pragma unroll
            for (int k = 0; k < BB*SS; ++k) ne += (g_flag[k] ? 1 : 0);
            const double loss_unm = g_acc[4] / fmax((double)ne, 1.0);
            out[0] = (float)(loss_center * (double)wc[0] +
                             loss_obj    * (double)wo[0] +
                             loss_unm    * (double)wu[0]);
        }
    }
}

// ---------------- launch ----------------
extern "C" void kernel_launch(void* const* d_in, const int* in_sizes, int n_in,
                              void* d_out, int out_size) {
    const float* pb     = (const float*)d_in[0];   // pred_boxes  [8,4,8192,7]
    const float* scores = (const float*)d_in[2];   // pred_scores [8,4,8192]
    const float* gtb    = (const float*)d_in[3];   // gt_boxes    [8,50,7]
    const int*   n_gt   = (const int*)d_in[5];     // [8]
    const float* wc     = (const float*)d_in[6];
    const float* wo     = (const float*)d_in[7];
    const float* wu     = (const float*)d_in[8];
    float* out = (float*)d_out;

    static bool attr_set = false;
    if (!attr_set) {
        cudaFuncSetAttribute(topk_kernel,
                             cudaFuncAttributeMaxDynamicSharedMemorySize,
                             2 * NN * sizeof(float));
        attr_set = true;
    }

    prep_kernel<<<(BSN + 255) / 256, 256>>>(pb);
    dim3 grid(MM / 2, SS, BB);
    topk_kernel<<<grid, 256, 2 * NN * sizeof(float)>>>(gtb, n_gt, scores);
    reduce_kernel<<<148, 256>>>(scores, gtb, out, wc, wo, wu);
}